// round 14
// baseline (speedup 1.0000x reference)
#include <cuda_runtime.h>
#include <cuda_bf16.h>

// Problem constants
#define CT   2048          // sequence length
#define CD   1024          // model dim
#define CH   16            // heads
#define CHD  64            // head dim
#define CB   4             // batch
#define CNQ  1152          // D + 2*HD  (qkv width)
#define CM   8192          // B*T rows

// Scratch (device globals; no allocation allowed)
__device__ float g_qkv[(size_t)CM * CNQ];   // [8192, 1152]
__device__ float g_y  [(size_t)CM * CD];    // [8192, 1024]

// ---------------------------------------------------------------------------
// Fast exp for x <= 0 (softmax weights). Avoids MUFU bottleneck:
// exp(x) = 2^z, z = x*log2(e);  z clamped at -30 (result ~1e-9, negligible
// vs row sum >= 1). Degree-6 Taylor of 2^f on [0,1): rel err ~8e-6.
// ---------------------------------------------------------------------------
__device__ __forceinline__ float fexp_neg(float x) {
    float z = x * 1.44269504088896f;
    z = fmaxf(z, -30.0f);
    float n = floorf(z);
    float f = z - n;                       // [0,1)
    float p = 1.54035304e-4f;
    p = fmaf(p, f, 1.33335581e-3f);
    p = fmaf(p, f, 9.61812911e-3f);
    p = fmaf(p, f, 5.55041087e-2f);
    p = fmaf(p, f, 2.40226507e-1f);
    p = fmaf(p, f, 6.93147181e-1f);
    p = fmaf(p, f, 1.0f);
    int ni = (int)n;                       // -30..0
    float sc = __int_as_float((ni + 127) << 23);   // 2^n
    return p * sc;
}

// Reductions within 16-lane row groups (xor 1,2,4,8 never crosses half-warp)
__device__ __forceinline__ float redmax16(float v) {
    #pragma unroll
    for (int o = 8; o > 0; o >>= 1)
        v = fmaxf(v, __shfl_xor_sync(0xffffffffu, v, o));
    return v;
}
__device__ __forceinline__ float redsum16(float v) {
    #pragma unroll
    for (int o = 8; o > 0; o >>= 1)
        v += __shfl_xor_sync(0xffffffffu, v, o);
    return v;
}

// ---------------------------------------------------------------------------
// SGEMM body: C[M,N] = A[M,K] @ B[K,N], all row-major fp32.
// 128x128 block, BK=8, 256 threads, 8x8 microtile, register prefetch.
// All dims here are multiples of the tile sizes (no bounds checks needed).
// ---------------------------------------------------------------------------
__device__ __forceinline__ void sgemm_body(const float* __restrict__ A,
                                           const float* __restrict__ Bm,
                                           float* __restrict__ C,
                                           int N, int K) {
    __shared__ float Ast[8][132];   // transposed A tile [k][m], pad 4
    __shared__ float Bs [8][132];   // B tile [k][n], pad 4

    const int tid  = threadIdx.x;
    const int tx   = tid & 15;
    const int ty   = tid >> 4;
    const int m0   = blockIdx.y * 128;
    const int n0   = blockIdx.x * 128;

    const int arow = tid >> 1;            // 0..127
    const int acol = (tid & 1) * 4;       // 0 or 4
    const int bkk  = tid >> 5;            // 0..7
    const int bcol = (tid & 31) * 4;      // 0..124

    const float* Ap = A  + (size_t)(m0 + arow) * K + acol;
    const float* Bp = Bm + (size_t)bkk * N + n0 + bcol;

    float acc[8][8];
    #pragma unroll
    for (int i = 0; i < 8; i++)
        #pragma unroll
        for (int j = 0; j < 8; j++) acc[i][j] = 0.0f;

    float4 av = *(const float4*)Ap;
    float4 bv = *(const float4*)Bp;

    for (int kt = 0; kt < K; kt += 8) {
        // commit prefetched tile to smem (A transposed: conflict-free mapping)
        Ast[acol + 0][arow] = av.x;
        Ast[acol + 1][arow] = av.y;
        Ast[acol + 2][arow] = av.z;
        Ast[acol + 3][arow] = av.w;
        *(float4*)&Bs[bkk][bcol] = bv;
        __syncthreads();

        if (kt + 8 < K) {                 // prefetch next tile
            av = *(const float4*)(Ap + kt + 8);
            bv = *(const float4*)(Bp + (size_t)(kt + 8) * N);
        }

        #pragma unroll
        for (int kk = 0; kk < 8; kk++) {
            float4 a0 = *(const float4*)&Ast[kk][ty * 8];
            float4 a1 = *(const float4*)&Ast[kk][ty * 8 + 4];
            float4 b0 = *(const float4*)&Bs [kk][tx * 8];
            float4 b1 = *(const float4*)&Bs [kk][tx * 8 + 4];
            float ar[8] = {a0.x, a0.y, a0.z, a0.w, a1.x, a1.y, a1.z, a1.w};
            float br[8] = {b0.x, b0.y, b0.z, b0.w, b1.x, b1.y, b1.z, b1.w};
            #pragma unroll
            for (int i = 0; i < 8; i++)
                #pragma unroll
                for (int j = 0; j < 8; j++)
                    acc[i][j] = fmaf(ar[i], br[j], acc[i][j]);
        }
        __syncthreads();
    }

    #pragma unroll
    for (int i = 0; i < 8; i++) {
        float* cp = C + (size_t)(m0 + ty * 8 + i) * N + n0 + tx * 8;
        *(float4*)cp       = make_float4(acc[i][0], acc[i][1], acc[i][2], acc[i][3]);
        *(float4*)(cp + 4) = make_float4(acc[i][4], acc[i][5], acc[i][6], acc[i][7]);
    }
}

__global__ __launch_bounds__(256) void qkv_gemm_kernel(const float* __restrict__ x,
                                                       const float* __restrict__ w_attn) {
    sgemm_body(x, w_attn, g_qkv, CNQ, CD);
}

__global__ __launch_bounds__(256) void proj_gemm_kernel(const float* __restrict__ w_proj,
                                                        float* __restrict__ out) {
    sgemm_body(g_y, w_proj, out, CD, CD);
}

// ---------------------------------------------------------------------------
// Flash attention (MQA: single shared K/V head). CTA = 128 queries of one
// (b,h); loops 64-wide KV tiles with online softmax. Scale folded into Q.
// smem: Qt[64][132] Kt[64][68] Vs[64][68] Pt[64][132]  = 100 KB (dynamic).
// ---------------------------------------------------------------------------
#define FLASH_SMEM_FLOATS (64*132 + 64*68 + 64*68 + 64*132)
#define FLASH_SMEM_BYTES  (FLASH_SMEM_FLOATS * 4)

__global__ __launch_bounds__(256) void flash_attn_kernel() {
    extern __shared__ float sm[];
    float* Qt = sm;                         // [d][r]  stride 132
    float* Kt = sm + 64 * 132;              // [d][c]  stride 68
    float* Vs = Kt + 64 * 68;               // [c][d]  stride 68
    float* Pt = Vs + 64 * 68;               // [c][r]  stride 132

    const int tid = threadIdx.x;
    const int tx  = tid & 15;
    const int ty  = tid >> 4;
    const int iq  = (CT / 128 - 1) - blockIdx.x;   // reversed: heavy blocks first
    const int h   = blockIdx.y;
    const int b   = blockIdx.z;
    const size_t bt = (size_t)b * CT;

    // --- load Q (scaled by 1/sqrt(64)), transposed, conflict-free ---
    {
        const int r  = tid >> 1;            // 0..127
        const int qb = tid & 1;
        const float* src = g_qkv + (bt + (size_t)iq * 128 + r) * CNQ + h * CHD;
        #pragma unroll
        for (int rep = 0; rep < 8; rep++) {
            int q = qb + rep * 2;           // 0..15
            float4 v = *(const float4*)(src + q * 4);
            Qt[(q * 4 + 0) * 132 + r] = v.x * 0.125f;
            Qt[(q * 4 + 1) * 132 + r] = v.y * 0.125f;
            Qt[(q * 4 + 2) * 132 + r] = v.z * 0.125f;
            Qt[(q * 4 + 3) * 132 + r] = v.w * 0.125f;
        }
    }

    float m_r[8], l_r[8], O[8][4];
    #pragma unroll
    for (int i = 0; i < 8; i++) {
        m_r[i] = -1e30f;
        l_r[i] = 0.0f;
        #pragma unroll
        for (int j = 0; j < 4; j++) O[i][j] = 0.0f;
    }

    const int jmax = 2 * iq + 1;            // last KV tile touching the diagonal
    for (int j = 0; j <= jmax; j++) {
        __syncthreads();                    // prev iteration's smem reads done

        // --- load K tile transposed (conflict-free store mapping) ---
        {
            const int c  = (tid >> 1) & 63;
            const int qb = (tid & 1) + ((tid >> 7) << 1);   // 0..3
            const float* src = g_qkv + (bt + (size_t)j * 64 + c) * CNQ + CD;
            #pragma unroll
            for (int rep = 0; rep < 4; rep++) {
                int q = qb + rep * 4;       // 0..15
                float4 v = *(const float4*)(src + q * 4);
                Kt[(q * 4 + 0) * 68 + c] = v.x;
                Kt[(q * 4 + 1) * 68 + c] = v.y;
                Kt[(q * 4 + 2) * 68 + c] = v.z;
                Kt[(q * 4 + 3) * 68 + c] = v.w;
            }
        }
        // --- load V tile natural layout (coalesced, conflict-free) ---
        {
            const int c  = tid >> 4;        // 0..15
            const int dq = (tid & 15) * 4;
            const float* src = g_qkv + (bt + (size_t)j * 64 + c) * CNQ + CD + CHD + dq;
            #pragma unroll
            for (int rep = 0; rep < 4; rep++) {
                float4 v = *(const float4*)(src + (size_t)rep * 16 * CNQ);
                *(float4*)&Vs[(c + rep * 16) * 68 + dq] = v;
            }
        }
        __syncthreads();

        // --- S = Q K^T (contraction over head dim) ---
        float s[8][4];
        #pragma unroll
        for (int i = 0; i < 8; i++)
            #pragma unroll
            for (int jj = 0; jj < 4; jj++) s[i][jj] = 0.0f;

        #pragma unroll 8
        for (int d = 0; d < 64; d++) {
            float4 q0 = *(const float4*)&Qt[d * 132 + ty * 8];
            float4 q1 = *(const float4*)&Qt[d * 132 + ty * 8 + 4];
            float4 kv = *(const float4*)&Kt[d * 68 + tx * 4];
            float qa[8] = {q0.x, q0.y, q0.z, q0.w, q1.x, q1.y, q1.z, q1.w};
            float kb[4] = {kv.x, kv.y, kv.z, kv.w};
            #pragma unroll
            for (int i = 0; i < 8; i++)
                #pragma unroll
                for (int jj = 0; jj < 4; jj++)
                    s[i][jj] = fmaf(qa[i], kb[jj], s[i][jj]);
        }

        // --- causal mask (only tiles overlapping the diagonal) ---
        if (j >= 2 * iq) {
            #pragma unroll
            for (int i = 0; i < 8; i++) {
                int rg = iq * 128 + ty * 8 + i;
                #pragma unroll
                for (int jj = 0; jj < 4; jj++) {
                    int cg = j * 64 + tx * 4 + jj;
                    if (cg > rg) s[i][jj] = -1e30f;
                }
            }
        }

        // --- online softmax update ---
        #pragma unroll
        for (int i = 0; i < 8; i++) {
            float mt = fmaxf(fmaxf(s[i][0], s[i][1]), fmaxf(s[i][2], s[i][3]));
            mt = redmax16(mt);
            float mn    = fmaxf(m_r[i], mt);
            float alpha = fexp_neg(m_r[i] - mn);
            m_r[i] = mn;
            float rs = 0.0f;
            #pragma unroll
            for (int jj = 0; jj < 4; jj++) {
                float p = fexp_neg(s[i][jj] - mn);
                s[i][jj] = p;
                rs += p;
            }
            l_r[i] = fmaf(l_r[i], alpha, rs);
            #pragma unroll
            for (int jj = 0; jj < 4; jj++) O[i][jj] *= alpha;
        }

        // --- stage P (transposed) through smem ---
        #pragma unroll
        for (int jj = 0; jj < 4; jj++) {
            int c = tx * 4 + jj;
            *(float4*)&Pt[c * 132 + ty * 8]     = make_float4(s[0][jj], s[1][jj], s[2][jj], s[3][jj]);
            *(float4*)&Pt[c * 132 + ty * 8 + 4] = make_float4(s[4][jj], s[5][jj], s[6][jj], s[7][jj]);
        }
        __syncthreads();

        // --- O += P V ---
        #pragma unroll 8
        for (int c = 0; c < 64; c++) {
            float4 p0 = *(const float4*)&Pt[c * 132 + ty * 8];
            float4 p1 = *(const float4*)&Pt[c * 132 + ty * 8 + 4];
            float4 vv = *(const float4*)&Vs[c * 68 + tx * 4];
            float pa[8] = {p0.x, p0.y, p0.z, p0.w, p1.x, p1.y, p1.z, p1.w};
            float vb[4] = {vv.x, vv.y, vv.z, vv.w};
            #pragma unroll
            for (int i = 0; i < 8; i++)
                #pragma unroll
                for (int jj = 0; jj < 4; jj++)
                    O[i][jj] = fmaf(pa[i], vb[jj], O[i][jj]);
        }
    }

    // --- epilogue: normalize and write y (layout [b*T+t, h*64+d]) ---
    #pragma unroll
    for (int i = 0; i < 8; i++) {
        float lt  = redsum16(l_r[i]);
        float inv = 1.0f / lt;
        float4 o = make_float4(O[i][0] * inv, O[i][1] * inv,
                               O[i][2] * inv, O[i][3] * inv);
        *(float4*)&g_y[(bt + (size_t)iq * 128 + ty * 8 + i) * CD + h * CHD + tx * 4] = o;
    }
}

// ---------------------------------------------------------------------------
extern "C" void kernel_launch(void* const* d_in, const int* in_sizes, int n_in,
                              void* d_out, int out_size) {
    (void)in_sizes; (void)n_in; (void)out_size;
    const float* x      = (const float*)d_in[0];
    const float* w_attn = (const float*)d_in[1];
    const float* w_proj = (const float*)d_in[2];
    float* out = (float*)d_out;

    // flash kernel needs 100 KB dynamic smem (idempotent, capture-safe)
    cudaFuncSetAttribute((const void*)flash_attn_kernel,
                         cudaFuncAttributeMaxDynamicSharedMemorySize,
                         FLASH_SMEM_BYTES);

    dim3 g1(CNQ / 128, CM / 128);      // (9, 64)
    qkv_gemm_kernel<<<g1, 256>>>(x, w_attn);

    dim3 g2(CT / 128, CH, CB);         // (16, 16, 4)
    flash_attn_kernel<<<g2, 256, FLASH_SMEM_BYTES>>>();

    dim3 g3(CD / 128, CM / 128);       // (8, 64)
    proj_gemm_kernel<<<g3, 256>>>(w_proj, out);
}

// round 15
// speedup vs baseline: 1.0030x; 1.0030x over previous
#include <cuda_runtime.h>
#include <cuda_bf16.h>

// Problem constants
#define CT   2048          // sequence length
#define CD   1024          // model dim
#define CH   16            // heads
#define CHD  64            // head dim
#define CB   4             // batch
#define CNQ  1152          // D + 2*HD  (qkv width)
#define CM   8192          // B*T rows

// Scratch (device globals; no allocation allowed)
__device__ float g_qkv[(size_t)CM * CNQ];   // [8192, 1152]
__device__ float g_y  [(size_t)CM * CD];    // [8192, 1024]

// ---------------------------------------------------------------------------
// Fast exp for x <= 0 (softmax weights). Avoids MUFU bottleneck:
// exp(x) = 2^z, z = x*log2(e);  z clamped at -30 (result ~1e-9, negligible
// vs row sum >= 1). Degree-6 Taylor of 2^f on [0,1): rel err ~8e-6.
// ---------------------------------------------------------------------------
__device__ __forceinline__ float fexp_neg(float x) {
    float z = x * 1.44269504088896f;
    z = fmaxf(z, -30.0f);
    float n = floorf(z);
    float f = z - n;                       // [0,1)
    float p = 1.54035304e-4f;
    p = fmaf(p, f, 1.33335581e-3f);
    p = fmaf(p, f, 9.61812911e-3f);
    p = fmaf(p, f, 5.55041087e-2f);
    p = fmaf(p, f, 2.40226507e-1f);
    p = fmaf(p, f, 6.93147181e-1f);
    p = fmaf(p, f, 1.0f);
    int ni = (int)n;                       // -30..0
    float sc = __int_as_float((ni + 127) << 23);   // 2^n
    return p * sc;
}

// Reductions within 16-lane row groups (xor 1,2,4,8 never crosses half-warp)
__device__ __forceinline__ float redmax16(float v) {
    #pragma unroll
    for (int o = 8; o > 0; o >>= 1)
        v = fmaxf(v, __shfl_xor_sync(0xffffffffu, v, o));
    return v;
}
__device__ __forceinline__ float redsum16(float v) {
    #pragma unroll
    for (int o = 8; o > 0; o >>= 1)
        v += __shfl_xor_sync(0xffffffffu, v, o);
    return v;
}

// ---------------------------------------------------------------------------
// SGEMM body: C[M,N] = A[M,K] @ B[K,N], all row-major fp32.
// 128x128 block, BK=8, 256 threads, 8x8 microtile, register prefetch.
// All dims here are multiples of the tile sizes (no bounds checks needed).
// ---------------------------------------------------------------------------
__device__ __forceinline__ void sgemm_body(const float* __restrict__ A,
                                           const float* __restrict__ Bm,
                                           float* __restrict__ C,
                                           int N, int K) {
    __shared__ float Ast[8][132];   // transposed A tile [k][m], pad 4
    __shared__ float Bs [8][132];   // B tile [k][n], pad 4

    const int tid  = threadIdx.x;
    const int tx   = tid & 15;
    const int ty   = tid >> 4;
    const int m0   = blockIdx.y * 128;
    const int n0   = blockIdx.x * 128;

    const int arow = tid >> 1;            // 0..127
    const int acol = (tid & 1) * 4;       // 0 or 4
    const int bkk  = tid >> 5;            // 0..7
    const int bcol = (tid & 31) * 4;      // 0..124

    const float* Ap = A  + (size_t)(m0 + arow) * K + acol;
    const float* Bp = Bm + (size_t)bkk * N + n0 + bcol;

    float acc[8][8];
    #pragma unroll
    for (int i = 0; i < 8; i++)
        #pragma unroll
        for (int j = 0; j < 8; j++) acc[i][j] = 0.0f;

    float4 av = *(const float4*)Ap;
    float4 bv = *(const float4*)Bp;

    for (int kt = 0; kt < K; kt += 8) {
        // commit prefetched tile to smem (A transposed: conflict-free mapping)
        Ast[acol + 0][arow] = av.x;
        Ast[acol + 1][arow] = av.y;
        Ast[acol + 2][arow] = av.z;
        Ast[acol + 3][arow] = av.w;
        *(float4*)&Bs[bkk][bcol] = bv;
        __syncthreads();

        if (kt + 8 < K) {                 // prefetch next tile
            av = *(const float4*)(Ap + kt + 8);
            bv = *(const float4*)(Bp + (size_t)(kt + 8) * N);
        }

        #pragma unroll
        for (int kk = 0; kk < 8; kk++) {
            float4 a0 = *(const float4*)&Ast[kk][ty * 8];
            float4 a1 = *(const float4*)&Ast[kk][ty * 8 + 4];
            float4 b0 = *(const float4*)&Bs [kk][tx * 8];
            float4 b1 = *(const float4*)&Bs [kk][tx * 8 + 4];
            float ar[8] = {a0.x, a0.y, a0.z, a0.w, a1.x, a1.y, a1.z, a1.w};
            float br[8] = {b0.x, b0.y, b0.z, b0.w, b1.x, b1.y, b1.z, b1.w};
            #pragma unroll
            for (int i = 0; i < 8; i++)
                #pragma unroll
                for (int j = 0; j < 8; j++)
                    acc[i][j] = fmaf(ar[i], br[j], acc[i][j]);
        }
        __syncthreads();
    }

    #pragma unroll
    for (int i = 0; i < 8; i++) {
        float* cp = C + (size_t)(m0 + ty * 8 + i) * N + n0 + tx * 8;
        *(float4*)cp       = make_float4(acc[i][0], acc[i][1], acc[i][2], acc[i][3]);
        *(float4*)(cp + 4) = make_float4(acc[i][4], acc[i][5], acc[i][6], acc[i][7]);
    }
}

__global__ __launch_bounds__(256) void qkv_gemm_kernel(const float* __restrict__ x,
                                                       const float* __restrict__ w_attn) {
    sgemm_body(x, w_attn, g_qkv, CNQ, CD);
}

__global__ __launch_bounds__(256) void proj_gemm_kernel(const float* __restrict__ w_proj,
                                                        float* __restrict__ out) {
    sgemm_body(g_y, w_proj, out, CD, CD);
}

// ---------------------------------------------------------------------------
// Flash attention (MQA: single shared K/V head). CTA = 128 queries of one
// (b,h); loops 64-wide KV tiles with online softmax. Scale folded into Q.
// smem: Qt[64][132] Kt[64][68] Vs[64][68] Pt[64][132]  = 100 KB (dynamic).
// ---------------------------------------------------------------------------
#define FLASH_SMEM_FLOATS (64*132 + 64*68 + 64*68 + 64*132)
#define FLASH_SMEM_BYTES  (FLASH_SMEM_FLOATS * 4)

__global__ __launch_bounds__(256) void flash_attn_kernel() {
    extern __shared__ float sm[];
    float* Qt = sm;                         // [d][r]  stride 132
    float* Kt = sm + 64 * 132;              // [d][c]  stride 68
    float* Vs = Kt + 64 * 68;               // [c][d]  stride 68
    float* Pt = Vs + 64 * 68;               // [c][r]  stride 132

    const int tid = threadIdx.x;
    const int tx  = tid & 15;
    const int ty  = tid >> 4;
    const int iq  = (CT / 128 - 1) - blockIdx.x;   // reversed: heavy blocks first
    const int h   = blockIdx.y;
    const int b   = blockIdx.z;
    const size_t bt = (size_t)b * CT;

    // --- load Q (scaled by 1/sqrt(64)), transposed, conflict-free ---
    {
        const int r  = tid >> 1;            // 0..127
        const int qb = tid & 1;
        const float* src = g_qkv + (bt + (size_t)iq * 128 + r) * CNQ + h * CHD;
        #pragma unroll
        for (int rep = 0; rep < 8; rep++) {
            int q = qb + rep * 2;           // 0..15
            float4 v = *(const float4*)(src + q * 4);
            Qt[(q * 4 + 0) * 132 + r] = v.x * 0.125f;
            Qt[(q * 4 + 1) * 132 + r] = v.y * 0.125f;
            Qt[(q * 4 + 2) * 132 + r] = v.z * 0.125f;
            Qt[(q * 4 + 3) * 132 + r] = v.w * 0.125f;
        }
    }

    float m_r[8], l_r[8], O[8][4];
    #pragma unroll
    for (int i = 0; i < 8; i++) {
        m_r[i] = -1e30f;
        l_r[i] = 0.0f;
        #pragma unroll
        for (int j = 0; j < 4; j++) O[i][j] = 0.0f;
    }

    const int jmax = 2 * iq + 1;            // last KV tile touching the diagonal
    for (int j = 0; j <= jmax; j++) {
        __syncthreads();                    // prev iteration's smem reads done

        // --- load K tile transposed (conflict-free store mapping) ---
        {
            const int c  = (tid >> 1) & 63;
            const int qb = (tid & 1) + ((tid >> 7) << 1);   // 0..3
            const float* src = g_qkv + (bt + (size_t)j * 64 + c) * CNQ + CD;
            #pragma unroll
            for (int rep = 0; rep < 4; rep++) {
                int q = qb + rep * 4;       // 0..15
                float4 v = *(const float4*)(src + q * 4);
                Kt[(q * 4 + 0) * 68 + c] = v.x;
                Kt[(q * 4 + 1) * 68 + c] = v.y;
                Kt[(q * 4 + 2) * 68 + c] = v.z;
                Kt[(q * 4 + 3) * 68 + c] = v.w;
            }
        }
        // --- load V tile natural layout (coalesced, conflict-free) ---
        {
            const int c  = tid >> 4;        // 0..15
            const int dq = (tid & 15) * 4;
            const float* src = g_qkv + (bt + (size_t)j * 64 + c) * CNQ + CD + CHD + dq;
            #pragma unroll
            for (int rep = 0; rep < 4; rep++) {
                float4 v = *(const float4*)(src + (size_t)rep * 16 * CNQ);
                *(float4*)&Vs[(c + rep * 16) * 68 + dq] = v;
            }
        }
        __syncthreads();

        // --- S = Q K^T (contraction over head dim) ---
        float s[8][4];
        #pragma unroll
        for (int i = 0; i < 8; i++)
            #pragma unroll
            for (int jj = 0; jj < 4; jj++) s[i][jj] = 0.0f;

        #pragma unroll 8
        for (int d = 0; d < 64; d++) {
            float4 q0 = *(const float4*)&Qt[d * 132 + ty * 8];
            float4 q1 = *(const float4*)&Qt[d * 132 + ty * 8 + 4];
            float4 kv = *(const float4*)&Kt[d * 68 + tx * 4];
            float qa[8] = {q0.x, q0.y, q0.z, q0.w, q1.x, q1.y, q1.z, q1.w};
            float kb[4] = {kv.x, kv.y, kv.z, kv.w};
            #pragma unroll
            for (int i = 0; i < 8; i++)
                #pragma unroll
                for (int jj = 0; jj < 4; jj++)
                    s[i][jj] = fmaf(qa[i], kb[jj], s[i][jj]);
        }

        // --- causal mask (only tiles overlapping the diagonal) ---
        if (j >= 2 * iq) {
            #pragma unroll
            for (int i = 0; i < 8; i++) {
                int rg = iq * 128 + ty * 8 + i;
                #pragma unroll
                for (int jj = 0; jj < 4; jj++) {
                    int cg = j * 64 + tx * 4 + jj;
                    if (cg > rg) s[i][jj] = -1e30f;
                }
            }
        }

        // --- online softmax update ---
        #pragma unroll
        for (int i = 0; i < 8; i++) {
            float mt = fmaxf(fmaxf(s[i][0], s[i][1]), fmaxf(s[i][2], s[i][3]));
            mt = redmax16(mt);
            float mn    = fmaxf(m_r[i], mt);
            float alpha = fexp_neg(m_r[i] - mn);
            m_r[i] = mn;
            float rs = 0.0f;
            #pragma unroll
            for (int jj = 0; jj < 4; jj++) {
                float p = fexp_neg(s[i][jj] - mn);
                s[i][jj] = p;
                rs += p;
            }
            l_r[i] = fmaf(l_r[i], alpha, rs);
            #pragma unroll
            for (int jj = 0; jj < 4; jj++) O[i][jj] *= alpha;
        }

        // --- stage P (transposed) through smem ---
        #pragma unroll
        for (int jj = 0; jj < 4; jj++) {
            int c = tx * 4 + jj;
            *(float4*)&Pt[c * 132 + ty * 8]     = make_float4(s[0][jj], s[1][jj], s[2][jj], s[3][jj]);
            *(float4*)&Pt[c * 132 + ty * 8 + 4] = make_float4(s[4][jj], s[5][jj], s[6][jj], s[7][jj]);
        }
        __syncthreads();

        // --- O += P V ---
        #pragma unroll 8
        for (int c = 0; c < 64; c++) {
            float4 p0 = *(const float4*)&Pt[c * 132 + ty * 8];
            float4 p1 = *(const float4*)&Pt[c * 132 + ty * 8 + 4];
            float4 vv = *(const float4*)&Vs[c * 68 + tx * 4];
            float pa[8] = {p0.x, p0.y, p0.z, p0.w, p1.x, p1.y, p1.z, p1.w};
            float vb[4] = {vv.x, vv.y, vv.z, vv.w};
            #pragma unroll
            for (int i = 0; i < 8; i++)
                #pragma unroll
                for (int jj = 0; jj < 4; jj++)
                    O[i][jj] = fmaf(pa[i], vb[jj], O[i][jj]);
        }
    }

    // --- epilogue: normalize and write y (layout [b*T+t, h*64+d]) ---
    #pragma unroll
    for (int i = 0; i < 8; i++) {
        float lt  = redsum16(l_r[i]);
        float inv = 1.0f / lt;
        float4 o = make_float4(O[i][0] * inv, O[i][1] * inv,
                               O[i][2] * inv, O[i][3] * inv);
        *(float4*)&g_y[(bt + (size_t)iq * 128 + ty * 8 + i) * CD + h * CHD + tx * 4] = o;
    }
}

// ---------------------------------------------------------------------------
extern "C" void kernel_launch(void* const* d_in, const int* in_sizes, int n_in,
                              void* d_out, int out_size) {
    (void)in_sizes; (void)n_in; (void)out_size;
    const float* x      = (const float*)d_in[0];
    const float* w_attn = (const float*)d_in[1];
    const float* w_proj = (const float*)d_in[2];
    float* out = (float*)d_out;

    // flash kernel needs 100 KB dynamic smem (idempotent, capture-safe)
    cudaFuncSetAttribute((const void*)flash_attn_kernel,
                         cudaFuncAttributeMaxDynamicSharedMemorySize,
                         FLASH_SMEM_BYTES);

    dim3 g1(CNQ / 128, CM / 128);      // (9, 64)
    qkv_gemm_kernel<<<g1, 256>>>(x, w_attn);

    dim3 g2(CT / 128, CH, CB);         // (16, 16, 4)
    flash_attn_kernel<<<g2, 256, FLASH_SMEM_BYTES>>>();

    dim3 g3(CD / 128, CM / 128);       // (8, 64)
    proj_gemm_kernel<<<g3, 256>>>(w_proj, out);
}